// round 1
// baseline (speedup 1.0000x reference)
#include <cuda_runtime.h>
#include <mma.h>

using namespace nvcuda;

// Problem constants
#define HS 112
#define WS 112
#define CI 128
#define CO 256
#define HW (HS * WS)          // 12544
#define NB 32
#define MTOT (NB * HW)        // 401408

// Tiling
#define BM 128
#define BN 128
#define BK 32
#define LDA 48                // padded, multiple of 8, rows 32B-aligned
#define LDB 136               // padded, multiple of 8, rows 32B-aligned

__global__ __launch_bounds__(256, 1)
void binary_conv_tf32_kernel(const float* __restrict__ x,
                             const float* __restrict__ w,
                             float* __restrict__ out) {
    __shared__ float As[BM][LDA];   // 128 x 48 floats = 24.0 KB
    __shared__ float Bs[BK][LDB];   // 32 x 136 floats = 17.0 KB

    const int tileM = blockIdx.x;   // 0..3135
    const int tileN = blockIdx.y;   // 0..1

    const int tid  = threadIdx.x;
    const int wid  = tid >> 5;
    const int warpM = wid & 3;      // 4 warps along M
    const int warpN = wid >> 2;     // 2 warps along N

    // A-tile loader mapping: 256 threads, each loads 4 rows x 16B (float4)
    const int rIdx  = tid >> 3;     // 0..31
    const int lane8 = tid & 7;      // 0..7

    // Pre-decode the 4 pixel coordinates this thread loads (constant over K loop)
    int nn[4], hh[4], ww_[4];
#pragma unroll
    for (int i = 0; i < 4; i++) {
        int p   = tileM * BM + rIdx + i * 32;
        int n   = p / HW;
        int rem = p - n * HW;
        int h   = rem / WS;
        nn[i]  = n;
        hh[i]  = h;
        ww_[i] = rem - h * WS;
    }

    wmma::fragment<wmma::accumulator, 16, 16, 8, float> acc[2][4];
#pragma unroll
    for (int i = 0; i < 2; i++)
#pragma unroll
        for (int j = 0; j < 4; j++)
            wmma::fill_fragment(acc[i][j], 0.0f);

    // B-tile loader mapping: each thread loads one k-row segment of 16 floats
    const int kr = tid >> 3;          // 0..31
    const int cb = (tid & 7) * 16;    // 0..112 step 16

    for (int tap = 0; tap < 9; tap++) {
        const int dy = tap / 3 - 1;
        const int dx = tap - (tap / 3) * 3 - 1;

        for (int kc = 0; kc < CI / BK; kc++) {   // 4 chunks of 32 channels
            // ---- Load A tile: 128 output pixels x 32 input channels ----
#pragma unroll
            for (int i = 0; i < 4; i++) {
                const int r  = rIdx + i * 32;
                const int ih = hh[i] + dy;
                const int iw = ww_[i] + dx;
                float4 v = make_float4(0.f, 0.f, 0.f, 0.f);
                if ((unsigned)ih < (unsigned)HS && (unsigned)iw < (unsigned)WS) {
                    const float* src = x
                        + (((size_t)nn[i] * HS + ih) * WS + iw) * CI
                        + kc * BK + lane8 * 4;
                    v = *reinterpret_cast<const float4*>(src);
                }
                const int c0 = lane8 * 4;
                As[r][c0 + 0] = wmma::__float_to_tf32(v.x);
                As[r][c0 + 1] = wmma::__float_to_tf32(v.y);
                As[r][c0 + 2] = wmma::__float_to_tf32(v.z);
                As[r][c0 + 3] = wmma::__float_to_tf32(v.w);
            }

            // ---- Load B tile: 32 k-rows x 128 out-channels, binarize inline ----
            {
                const float* wp = w
                    + ((size_t)(tap * CI + kc * BK + kr)) * CO
                    + tileN * BN + cb;
#pragma unroll
                for (int j = 0; j < 4; j++) {
                    float4 v = *reinterpret_cast<const float4*>(wp + j * 4);
                    const int c0 = cb + j * 4;
                    Bs[kr][c0 + 0] = wmma::__float_to_tf32((float)((v.x > 0.f) - (v.x < 0.f)));
                    Bs[kr][c0 + 1] = wmma::__float_to_tf32((float)((v.y > 0.f) - (v.y < 0.f)));
                    Bs[kr][c0 + 2] = wmma::__float_to_tf32((float)((v.z > 0.f) - (v.z < 0.f)));
                    Bs[kr][c0 + 3] = wmma::__float_to_tf32((float)((v.w > 0.f) - (v.w < 0.f)));
                }
            }

            __syncthreads();

            // ---- MMA: 4 k-steps of 8 ----
#pragma unroll
            for (int kk = 0; kk < BK / 8; kk++) {
                wmma::fragment<wmma::matrix_a, 16, 16, 8, wmma::precision::tf32, wmma::row_major> af[2];
                wmma::fragment<wmma::matrix_b, 16, 16, 8, wmma::precision::tf32, wmma::row_major> bf[4];
#pragma unroll
                for (int i = 0; i < 2; i++)
                    wmma::load_matrix_sync(af[i], &As[warpM * 32 + i * 16][kk * 8], LDA);
#pragma unroll
                for (int j = 0; j < 4; j++)
                    wmma::load_matrix_sync(bf[j], &Bs[kk * 8][warpN * 64 + j * 16], LDB);
#pragma unroll
                for (int i = 0; i < 2; i++)
#pragma unroll
                    for (int j = 0; j < 4; j++)
                        wmma::mma_sync(acc[i][j], af[i], bf[j], acc[i][j]);
            }

            __syncthreads();
        }
    }

    // ---- Epilogue: store 32x64 per warp directly to global (row stride CO) ----
#pragma unroll
    for (int i = 0; i < 2; i++) {
#pragma unroll
        for (int j = 0; j < 4; j++) {
            const size_t row0 = (size_t)tileM * BM + warpM * 32 + i * 16;
            const int    col0 = tileN * BN + warpN * 64 + j * 16;
            wmma::store_matrix_sync(out + row0 * CO + col0, acc[i][j], CO, wmma::mem_row_major);
        }
    }
}

extern "C" void kernel_launch(void* const* d_in, const int* in_sizes, int n_in,
                              void* d_out, int out_size) {
    const float* x = (const float*)d_in[0];   // (32,112,112,128) fp32 NHWC
    const float* w = (const float*)d_in[1];   // (3,3,128,256) fp32 HWIO
    float* out = (float*)d_out;               // (32,112,112,256) fp32

    dim3 grid(MTOT / BM, CO / BN);            // (3136, 2)
    dim3 block(256);
    binary_conv_tf32_kernel<<<grid, block>>>(x, w, out);
}

// round 5
// speedup vs baseline: 5.3713x; 5.3713x over previous
#include <cuda_runtime.h>
#include <cuda_fp16.h>
#include <cstdint>

// ---------------- problem constants ----------------
#define HS 112
#define WS 112
#define CI 128
#define CO 256
#define HW (HS * WS)            // 12544
#define MTOT (32 * HW)          // 401408
#define KTOT (9 * CI)           // 1152

// ---------------- tiling ----------------
#define BM 128
#define BN 128
#define BK 64                   // fp16 k-chunk -> 128B smem rows
#define NKT 18                  // 2 channel-halves x 9 taps
#define STAGES 3
#define A_OFF 0
#define B_OFF 16384
#define STAGE_BYTES 32768
#define SMEM_TOTAL (STAGES * STAGE_BYTES)   // 98304

// fp16 copies of inputs (static device scratch — allowed)
__device__ __align__(16) __half g_xh[(size_t)MTOT * CI];   // NHWC fp16
__device__ __align__(16) __half g_wb[CO * KTOT];           // [co][tap*128+ci] fp16 sign

__device__ __forceinline__ uint32_t smem_u32(const void* p) {
    uint32_t a;
    asm("{ .reg .u64 t; cvta.to.shared.u64 t, %1; cvt.u32.u64 %0, t; }" : "=r"(a) : "l"(p));
    return a;
}

// ---------------- prepass: x -> fp16 ----------------
__global__ void convert_x_kernel(const float4* __restrict__ x) {
    size_t i = (size_t)blockIdx.x * blockDim.x + threadIdx.x;   // 6422528 threads exactly
    float4 a = x[2 * i];
    float4 b = x[2 * i + 1];
    union { uint4 u; __half2 h[4]; } U;
    U.h[0] = __floats2half2_rn(a.x, a.y);
    U.h[1] = __floats2half2_rn(a.z, a.w);
    U.h[2] = __floats2half2_rn(b.x, b.y);
    U.h[3] = __floats2half2_rn(b.z, b.w);
    reinterpret_cast<uint4*>(g_xh)[i] = U.u;
}

// ---------------- prepass: binarize + transpose w ----------------
__global__ void binarize_kernel(const float* __restrict__ w) {
    int kk = blockIdx.x;          // 0..1151  (tap*128+ci)
    int n  = threadIdx.x;         // 0..255
    float v = w[(size_t)kk * CO + n];
    g_wb[(size_t)n * KTOT + kk] = __float2half((float)((v > 0.f) - (v < 0.f)));
}

// ---------------- main kernel ----------------
extern __shared__ __align__(1024) unsigned char smem_raw[];

__global__ __launch_bounds__(256, 2)
void conv_hmma_kernel(float* __restrict__ out) {
    const int tid = threadIdx.x;
    const int l   = tid & 31;
    const int wid = tid >> 5;
    const int warpM = wid & 3;     // 4 warps x 32 rows
    const int warpN = wid >> 2;    // 2 warps x 64 cols
    const uint32_t smem = smem_u32(smem_raw);

    // ---- loader precompute: thread -> (row lr, 64B half of the 128B row) ----
    const int lr = tid >> 1;                   // 0..127
    const int p  = blockIdx.x * BM + lr;
    const int n_ = p / HW;
    int rem = p - n_ * HW;
    const int h_ = rem / WS;
    const int w_ = rem - h_ * WS;

    uint32_t dsw[4];                           // swizzled dst offsets within a tile
#pragma unroll
    for (int i = 0; i < 4; i++) {
        int c = (tid & 1) * 4 + i;             // 16B chunk 0..7
        uint32_t o = (uint32_t)(lr * 128 + c * 16);
        dsw[i] = o ^ ((uint32_t)(lr & 7) << 4);
    }
    const __half* bsrc_base = g_wb + (size_t)(blockIdx.y * BN + lr) * KTOT + (tid & 1) * 32;

    // ---- ldmatrix address components: row base + row-derived XOR, col base ----
    // final addr = stage + rowbase + ((colbase + kk*32) ^ sw)   (col <= 112, XOR stays in-row)
    uint32_t a_rb[2], a_sw[2], a_cb;
    uint32_t b_rb[4], b_sw[4], b_cb;
#pragma unroll
    for (int mt = 0; mt < 2; mt++) {
        int r = warpM * 32 + mt * 16 + (l & 15);
        a_rb[mt] = A_OFF + (uint32_t)(r * 128);
        a_sw[mt] = (uint32_t)(r & 7) << 4;
    }
    a_cb = (uint32_t)(l >> 4) * 16;
#pragma unroll
    for (int ntp = 0; ntp < 4; ntp++) {
        int r = warpN * 64 + ntp * 16 + ((l >> 4) << 3) + (l & 7);
        b_rb[ntp] = B_OFF + (uint32_t)(r * 128);
        b_sw[ntp] = (uint32_t)(r & 7) << 4;
    }
    b_cb = (uint32_t)((l >> 3) & 1) * 16;

    float acc[2][8][4];
#pragma unroll
    for (int mt = 0; mt < 2; mt++)
#pragma unroll
        for (int nt = 0; nt < 8; nt++)
#pragma unroll
            for (int c = 0; c < 4; c++) acc[mt][nt][c] = 0.f;

    // ---- async stage loader ----
    auto issue = [&](int kt) {
        const int c2  = kt / 9;                 // channel half (outer -> A L1 reuse over taps)
        const int tap = kt - c2 * 9;
        const int dy  = tap / 3 - 1;
        const int dx  = tap - (tap / 3) * 3 - 1;
        const uint32_t sa = smem + (uint32_t)(kt % STAGES) * STAGE_BYTES;

        const int ih = h_ + dy, iw = w_ + dx;
        const bool valid = ((unsigned)ih < (unsigned)HS) && ((unsigned)iw < (unsigned)WS);
        const int ihc = valid ? ih : 0, iwc = valid ? iw : 0;
        const __half* asrc = g_xh + (((size_t)n_ * HS + ihc) * WS + iwc) * CI
                           + c2 * 64 + (tid & 1) * 32;
        const unsigned zf = valid ? 16u : 0u;
#pragma unroll
        for (int i = 0; i < 4; i++)
            asm volatile("cp.async.cg.shared.global [%0], [%1], 16, %2;"
                         :: "r"(sa + A_OFF + dsw[i]), "l"(asrc + i * 8), "r"(zf));
        const __half* bs = bsrc_base + tap * CI + c2 * 64;
#pragma unroll
        for (int i = 0; i < 4; i++)
            asm volatile("cp.async.cg.shared.global [%0], [%1], 16;"
                         :: "r"(sa + B_OFF + dsw[i]), "l"(bs + i * 8));
    };

    issue(0); asm volatile("cp.async.commit_group;" ::: "memory");
    issue(1); asm volatile("cp.async.commit_group;" ::: "memory");

    for (int kt = 0; kt < NKT; kt++) {
        asm volatile("cp.async.wait_group 1;" ::: "memory");
        __syncthreads();
        if (kt + 2 < NKT) issue(kt + 2);
        asm volatile("cp.async.commit_group;" ::: "memory");

        const uint32_t sbase = smem + (uint32_t)(kt % STAGES) * STAGE_BYTES;
#pragma unroll
        for (int kk = 0; kk < 4; kk++) {
            uint32_t a[2][4], b[4][4];
#pragma unroll
            for (int mt = 0; mt < 2; mt++) {
                const uint32_t addr = sbase + a_rb[mt] + ((a_cb + kk * 32) ^ a_sw[mt]);
                asm volatile("ldmatrix.sync.aligned.m8n8.x4.shared.b16 {%0,%1,%2,%3}, [%4];"
                             : "=r"(a[mt][0]), "=r"(a[mt][1]), "=r"(a[mt][2]), "=r"(a[mt][3])
                             : "r"(addr));
            }
#pragma unroll
            for (int ntp = 0; ntp < 4; ntp++) {
                const uint32_t addr = sbase + b_rb[ntp] + ((b_cb + kk * 32) ^ b_sw[ntp]);
                asm volatile("ldmatrix.sync.aligned.m8n8.x4.shared.b16 {%0,%1,%2,%3}, [%4];"
                             : "=r"(b[ntp][0]), "=r"(b[ntp][1]), "=r"(b[ntp][2]), "=r"(b[ntp][3])
                             : "r"(addr));
            }
#pragma unroll
            for (int mt = 0; mt < 2; mt++)
#pragma unroll
                for (int nt = 0; nt < 8; nt++) {
                    const uint32_t b0 = b[nt >> 1][(nt & 1) * 2];
                    const uint32_t b1 = b[nt >> 1][(nt & 1) * 2 + 1];
                    asm volatile(
                        "mma.sync.aligned.m16n8k16.row.col.f32.f16.f16.f32 "
                        "{%0,%1,%2,%3}, {%4,%5,%6,%7}, {%8,%9}, {%0,%1,%2,%3};"
                        : "+f"(acc[mt][nt][0]), "+f"(acc[mt][nt][1]),
                          "+f"(acc[mt][nt][2]), "+f"(acc[mt][nt][3])
                        : "r"(a[mt][0]), "r"(a[mt][1]), "r"(a[mt][2]), "r"(a[mt][3]),
                          "r"(b0), "r"(b1));
                }
        }
    }

    // ---- epilogue: direct global stores (float2 pairs) ----
    float* ob = out + ((size_t)blockIdx.x * BM + warpM * 32 + (l >> 2)) * CO
              + blockIdx.y * BN + warpN * 64 + (l & 3) * 2;
#pragma unroll
    for (int mt = 0; mt < 2; mt++)
#pragma unroll
        for (int nt = 0; nt < 8; nt++) {
            float* o0 = ob + (size_t)(mt * 16) * CO + nt * 8;
            float2 v0 = make_float2(acc[mt][nt][0], acc[mt][nt][1]);
            float2 v1 = make_float2(acc[mt][nt][2], acc[mt][nt][3]);
            *reinterpret_cast<float2*>(o0) = v0;
            *reinterpret_cast<float2*>(o0 + 8 * CO) = v1;
        }
}

// ---------------- launch ----------------
extern "C" void kernel_launch(void* const* d_in, const int* in_sizes, int n_in,
                              void* d_out, int out_size) {
    const float* x = (const float*)d_in[0];   // (32,112,112,128) fp32 NHWC
    const float* w = (const float*)d_in[1];   // (3,3,128,256) fp32 HWIO
    float* out = (float*)d_out;               // (32,112,112,256) fp32

    static bool init = false;
    if (!init) {
        cudaFuncSetAttribute(conv_hmma_kernel,
                             cudaFuncAttributeMaxDynamicSharedMemorySize, SMEM_TOTAL);
        init = true;
    }

    convert_x_kernel<<<25088, 256>>>((const float4*)x);   // 25088*256*8 == 51380224 elems
    binarize_kernel<<<KTOT, CO>>>(w);

    dim3 grid(MTOT / BM, CO / BN);            // (3136, 2)
    conv_hmma_kernel<<<grid, 256, SMEM_TOTAL>>>(out);
}

// round 6
// speedup vs baseline: 8.1842x; 1.5237x over previous
#include <cuda_runtime.h>
#include <cuda_fp16.h>
#include <cstdint>

// ---------------- problem constants ----------------
#define HS 112
#define WS 112
#define CI 128
#define CO 256
#define NIMG 32
#define TYN 56
#define TXN 56
#define NT_IMG (TYN * TXN)          // 3136 winograd tiles per image
#define MTILES (NIMG * NT_IMG)      // 100352 GEMM rows
#define VPLANE ((size_t)MTILES * CI)  // elements per coord plane
#define UPLANE (CO * CI)            // 32768

// ---------------- GEMM tiling ----------------
#define BMT 64                  // winograd tiles per CTA
#define BN 64                   // out channels per CTA
#define STAGE_B 16384           // A 8KB + B 8KB per (coord, k64) chunk
#define NSTG 4
#define SMEM_TOTAL (NSTG * STAGE_B)   // 65536

// static device scratch
__device__ __align__(16) __half g_V[16 * VPLANE];     // 411 MB transformed input
__device__ __align__(16) __half g_U[16 * UPLANE];     // 1 MB transformed binary filters

__device__ __forceinline__ uint32_t smem_u32(const void* p) {
    uint32_t a;
    asm("{ .reg .u64 t; cvta.to.shared.u64 t, %1; cvt.u32.u64 %0, t; }" : "=r"(a) : "l"(p));
    return a;
}

// ---------------- U = G sign(g) G^T  (exact in fp16) ----------------
__global__ void wino_filter_kernel(const float* __restrict__ wsrc) {
    const int k = threadIdx.x;    // 0..127 (ci)
    const int n = blockIdx.x;     // 0..255 (co)
    float s[3][3];
#pragma unroll
    for (int ky = 0; ky < 3; ky++)
#pragma unroll
        for (int kx = 0; kx < 3; kx++) {
            float v = wsrc[((size_t)(ky * 3 + kx) * CI + k) * CO + n];
            s[ky][kx] = (float)((v > 0.f) - (v < 0.f));
        }
    float t[4][3];
#pragma unroll
    for (int j = 0; j < 3; j++) {
        t[0][j] = s[0][j];
        t[1][j] = 0.5f * (s[0][j] + s[1][j] + s[2][j]);
        t[2][j] = 0.5f * (s[0][j] - s[1][j] + s[2][j]);
        t[3][j] = s[2][j];
    }
#pragma unroll
    for (int i = 0; i < 4; i++) {
        float u0 = t[i][0];
        float u1 = 0.5f * (t[i][0] + t[i][1] + t[i][2]);
        float u2 = 0.5f * (t[i][0] - t[i][1] + t[i][2]);
        float u3 = t[i][2];
        g_U[(size_t)(i * 4 + 0) * UPLANE + n * CI + k] = __float2half(u0);
        g_U[(size_t)(i * 4 + 1) * UPLANE + n * CI + k] = __float2half(u1);
        g_U[(size_t)(i * 4 + 2) * UPLANE + n * CI + k] = __float2half(u2);
        g_U[(size_t)(i * 4 + 3) * UPLANE + n * CI + k] = __float2half(u3);
    }
}

// ---------------- V = B^T d B  per tile, per channel pair ----------------
__global__ __launch_bounds__(256)
void wino_input_kernel(const float* __restrict__ x) {
    const int w    = threadIdx.x >> 5;
    const int lane = threadIdx.x & 31;
    const int tile = blockIdx.x * 4 + (w >> 1);
    const int ch   = (w & 1) * 64 + lane * 2;

    const int nimg = tile / NT_IMG;
    const int rr   = tile - nimg * NT_IMG;
    const int ty   = rr / TXN;
    const int tx   = rr - ty * TXN;

    float a[4][4], b[4][4];
#pragma unroll
    for (int i = 0; i < 4; i++) {
        const int ih = 2 * ty - 1 + i;
#pragma unroll
        for (int j = 0; j < 4; j++) {
            const int iw = 2 * tx - 1 + j;
            float2 v = make_float2(0.f, 0.f);
            if ((unsigned)ih < (unsigned)HS && (unsigned)iw < (unsigned)WS)
                v = *reinterpret_cast<const float2*>(
                    x + (((size_t)nimg * HS + ih) * WS + iw) * CI + ch);
            a[i][j] = v.x; b[i][j] = v.y;
        }
    }
    float ma[4][4], mb[4][4];
#pragma unroll
    for (int j = 0; j < 4; j++) {
        ma[0][j] = a[0][j] - a[2][j];  mb[0][j] = b[0][j] - b[2][j];
        ma[1][j] = a[1][j] + a[2][j];  mb[1][j] = b[1][j] + b[2][j];
        ma[2][j] = a[2][j] - a[1][j];  mb[2][j] = b[2][j] - b[1][j];
        ma[3][j] = a[1][j] - a[3][j];  mb[3][j] = b[1][j] - b[3][j];
    }
    __half* dst = g_V + (size_t)tile * CI + ch;
#pragma unroll
    for (int i = 0; i < 4; i++) {
        float va[4], vb[4];
        va[0] = ma[i][0] - ma[i][2];  vb[0] = mb[i][0] - mb[i][2];
        va[1] = ma[i][1] + ma[i][2];  vb[1] = mb[i][1] + mb[i][2];
        va[2] = ma[i][2] - ma[i][1];  vb[2] = mb[i][2] - mb[i][1];
        va[3] = ma[i][1] - ma[i][3];  vb[3] = mb[i][1] - mb[i][3];
#pragma unroll
        for (int j = 0; j < 4; j++)
            *reinterpret_cast<__half2*>(dst + (size_t)(i * 4 + j) * VPLANE) =
                __floats2half2_rn(va[j], vb[j]);
    }
}

// ---------------- GEMM over 16 coords with fused output transform ----------------
extern __shared__ __align__(1024) unsigned char smem_raw[];

__global__ __launch_bounds__(256, 2)
void wino_gemm_kernel(float* __restrict__ out) {
    const int tid = threadIdx.x;
    const int l   = tid & 31;
    const int wid = tid >> 5;
    const int warpM = wid & 3;     // 4 warps x 16 tile-rows
    const int warpN = wid >> 2;    // 2 warps x 32 cols
    const uint32_t smem = smem_u32(smem_raw);

    // ---- cp.async loader mapping: row lr (0..63), 32B chunk lc (0..3) ----
    const int lr = tid >> 2;
    const int lc = tid & 3;
    const uint32_t dst0 = ((uint32_t)(lr * 128 + lc * 32)) ^ ((uint32_t)(lr & 7) << 4);
    const uint32_t dst1 = dst0 ^ 16u;
    const __half* aV = g_V + ((size_t)blockIdx.y * BMT + lr) * CI + lc * 16;
    const __half* bU = g_U + ((size_t)blockIdx.x * BN  + lr) * CI + lc * 16;

    // ---- ldmatrix address components ----
    const uint32_t a_rb = (uint32_t)((warpM * 16 + (l & 15)) * 128);
    const uint32_t a_sw = (uint32_t)(l & 7) << 4;
    const uint32_t a_cb = (uint32_t)(l >> 4) * 16;
    uint32_t b_rb[2], b_sw[2];
#pragma unroll
    for (int ntp = 0; ntp < 2; ntp++) {
        int r = warpN * 32 + ntp * 16 + ((l >> 4) << 3) + (l & 7);
        b_rb[ntp] = 8192u + (uint32_t)(r * 128);
        b_sw[ntp] = (uint32_t)(r & 7) << 4;
    }
    const uint32_t b_cb = (uint32_t)((l >> 3) & 1) * 16;

    float oacc[4][16];
#pragma unroll
    for (int p = 0; p < 4; p++)
#pragma unroll
        for (int q = 0; q < 16; q++) oacc[p][q] = 0.f;

    auto issue = [&](int cs) {
        const int c  = cs >> 1;
        const int kt = cs & 1;
        const uint32_t sb = smem + (uint32_t)(cs & (NSTG - 1)) * STAGE_B;
        const __half* as = aV + (size_t)c * VPLANE + kt * 64;
        asm volatile("cp.async.cg.shared.global [%0], [%1], 16;" :: "r"(sb + dst0), "l"(as));
        asm volatile("cp.async.cg.shared.global [%0], [%1], 16;" :: "r"(sb + dst1), "l"(as + 8));
        const __half* bs = bU + (size_t)c * UPLANE + kt * 64;
        asm volatile("cp.async.cg.shared.global [%0], [%1], 16;" :: "r"(sb + 8192 + dst0), "l"(bs));
        asm volatile("cp.async.cg.shared.global [%0], [%1], 16;" :: "r"(sb + 8192 + dst1), "l"(bs + 8));
    };

    issue(0); asm volatile("cp.async.commit_group;" ::: "memory");
    issue(1); asm volatile("cp.async.commit_group;" ::: "memory");
    issue(2); asm volatile("cp.async.commit_group;" ::: "memory");

    const int AT[2][4] = {{1, 1, 1, 0}, {0, 1, -1, -1}};

#pragma unroll
    for (int c = 0; c < 16; c++) {
        float tacc[16];
#pragma unroll
        for (int q = 0; q < 16; q++) tacc[q] = 0.f;

#pragma unroll
        for (int kt = 0; kt < 2; kt++) {
            const int cs = c * 2 + kt;
            asm volatile("cp.async.wait_group 2;" ::: "memory");
            __syncthreads();
            if (cs + 3 < 32) issue(cs + 3);
            asm volatile("cp.async.commit_group;" ::: "memory");

            const uint32_t sb = smem + (uint32_t)(cs & (NSTG - 1)) * STAGE_B;
#pragma unroll
            for (int kk = 0; kk < 4; kk++) {
                uint32_t a[4], b[2][4];
                {
                    const uint32_t addr = sb + a_rb + ((a_cb + kk * 32) ^ a_sw);
                    asm volatile("ldmatrix.sync.aligned.m8n8.x4.shared.b16 {%0,%1,%2,%3}, [%4];"
                                 : "=r"(a[0]), "=r"(a[1]), "=r"(a[2]), "=r"(a[3]) : "r"(addr));
                }
#pragma unroll
                for (int ntp = 0; ntp < 2; ntp++) {
                    const uint32_t addr = sb + b_rb[ntp] + ((b_cb + kk * 32) ^ b_sw[ntp]);
                    asm volatile("ldmatrix.sync.aligned.m8n8.x4.shared.b16 {%0,%1,%2,%3}, [%4];"
                                 : "=r"(b[ntp][0]), "=r"(b[ntp][1]), "=r"(b[ntp][2]), "=r"(b[ntp][3])
                                 : "r"(addr));
                }
#pragma unroll
                for (int nt = 0; nt < 4; nt++) {
                    const uint32_t b0 = b[nt >> 1][(nt & 1) * 2];
                    const uint32_t b1 = b[nt >> 1][(nt & 1) * 2 + 1];
                    asm volatile(
                        "mma.sync.aligned.m16n8k16.row.col.f32.f16.f16.f32 "
                        "{%0,%1,%2,%3}, {%4,%5,%6,%7}, {%8,%9}, {%0,%1,%2,%3};"
                        : "+f"(tacc[nt * 4 + 0]), "+f"(tacc[nt * 4 + 1]),
                          "+f"(tacc[nt * 4 + 2]), "+f"(tacc[nt * 4 + 3])
                        : "r"(a[0]), "r"(a[1]), "r"(a[2]), "r"(a[3]), "r"(b0), "r"(b1));
                }
            }
        }

        // fused output transform: out[py][px] += AT[py][cy]*AT[px][cx] * M_c
        const int cy = c >> 2, cx = c & 3;
#pragma unroll
        for (int py = 0; py < 2; py++)
#pragma unroll
            for (int px = 0; px < 2; px++) {
                const int alpha = AT[py][cy] * AT[px][cx];
                if (alpha == 1) {
#pragma unroll
                    for (int q = 0; q < 16; q++) oacc[py * 2 + px][q] += tacc[q];
                } else if (alpha == -1) {
#pragma unroll
                    for (int q = 0; q < 16; q++) oacc[py * 2 + px][q] -= tacc[q];
                }
            }
    }

    // ---- store: each thread covers 2 tile-rows x 4 n-blocks x 4 pixels ----
    const int colb = blockIdx.x * BN + warpN * 32 + (l & 3) * 2;
#pragma unroll
    for (int rsel = 0; rsel < 2; rsel++) {
        const int t = blockIdx.y * BMT + warpM * 16 + (l >> 2) + rsel * 8;
        const int nimg = t / NT_IMG;
        const int rr   = t - nimg * NT_IMG;
        const int ty   = rr / TXN;
        const int tx   = rr - ty * TXN;
#pragma unroll
        for (int py = 0; py < 2; py++)
#pragma unroll
            for (int px = 0; px < 2; px++) {
                float* o = out + (((size_t)nimg * HS + 2 * ty + py) * WS + (2 * tx + px)) * CO + colb;
                const int p = py * 2 + px;
#pragma unroll
                for (int nt = 0; nt < 4; nt++)
                    *reinterpret_cast<float2*>(o + nt * 8) =
                        make_float2(oacc[p][nt * 4 + rsel * 2], oacc[p][nt * 4 + rsel * 2 + 1]);
            }
    }
}

// ---------------- launch ----------------
extern "C" void kernel_launch(void* const* d_in, const int* in_sizes, int n_in,
                              void* d_out, int out_size) {
    const float* x = (const float*)d_in[0];   // (32,112,112,128) fp32 NHWC
    const float* w = (const float*)d_in[1];   // (3,3,128,256) fp32 HWIO
    float* out = (float*)d_out;               // (32,112,112,256) fp32

    static bool init = false;
    if (!init) {
        cudaFuncSetAttribute(wino_gemm_kernel,
                             cudaFuncAttributeMaxDynamicSharedMemorySize, SMEM_TOTAL);
        init = true;
    }

    wino_filter_kernel<<<CO, CI>>>(w);
    wino_input_kernel<<<MTILES / 4, 256>>>(x);
    wino_gemm_kernel<<<dim3(CO / BN, MTILES / BMT), 256, SMEM_TOTAL>>>(out);   // (4, 1568)
}